// round 2
// baseline (speedup 1.0000x reference)
#include <cuda_runtime.h>

#define BT   8192   // B*T
#define DMM  1024
#define HN   16
#define DHD  64
#define TSEQ 2048
#define BATCH 4

// Scratch (allocation-free rule: __device__ globals)
__device__ float g_q[BT * DMM];        // Q projection  [8192,1024]
__device__ float g_kv[BT * 2 * DMM];   // KV projection [8192,2048]
__device__ float g_attn[BT * DMM];     // attention out [8192,1024]

// ----------------------------------------------------------------------------
// Classic fp32 tiled GEMM: C[M,N] = A[M,K] @ B[K,N] (+bias), row-major.
// 128x128 tile, BK=8, 256 threads, 8x8 per-thread microtile.
// All dims here are multiples of 128, no bounds checks needed.
// ----------------------------------------------------------------------------
__global__ __launch_bounds__(256) void sgemm_kernel(
    const float* __restrict__ A, const float* __restrict__ B,
    float* __restrict__ C, int M, int N, int K, const float* __restrict__ bias)
{
    __shared__ float As[8][128];
    __shared__ float Bs[8][128];
    int tid = threadIdx.x;
    int tx = tid & 15, ty = tid >> 4;
    const float* Ap = A + (size_t)blockIdx.y * 128 * K;
    const float* Bp = B + blockIdx.x * 128;
    float acc[8][8] = {};
    int aRow = tid >> 1, aCol = (tid & 1) * 4;   // A tile 128x8
    int bRow = tid >> 5, bCol = (tid & 31) * 4;  // B tile 8x128

    for (int k0 = 0; k0 < K; k0 += 8) {
        float4 a4 = *(const float4*)(Ap + (size_t)aRow * K + k0 + aCol);
        As[aCol + 0][aRow] = a4.x;
        As[aCol + 1][aRow] = a4.y;
        As[aCol + 2][aRow] = a4.z;
        As[aCol + 3][aRow] = a4.w;
        *(float4*)&Bs[bRow][bCol] = *(const float4*)(Bp + (size_t)(k0 + bRow) * N + bCol);
        __syncthreads();
        #pragma unroll
        for (int k = 0; k < 8; k++) {
            float ra[8], rb[8];
            #pragma unroll
            for (int i = 0; i < 8; i++) ra[i] = As[k][ty * 8 + i];
            #pragma unroll
            for (int j = 0; j < 8; j++) rb[j] = Bs[k][tx * 8 + j];
            #pragma unroll
            for (int i = 0; i < 8; i++)
                #pragma unroll
                for (int j = 0; j < 8; j++)
                    acc[i][j] = fmaf(ra[i], rb[j], acc[i][j]);
        }
        __syncthreads();
    }
    #pragma unroll
    for (int i = 0; i < 8; i++) {
        size_t row = (size_t)blockIdx.y * 128 + ty * 8 + i;
        #pragma unroll
        for (int j = 0; j < 8; j += 4) {
            int col = blockIdx.x * 128 + tx * 8 + j;
            float4 v = make_float4(acc[i][j], acc[i][j+1], acc[i][j+2], acc[i][j+3]);
            if (bias) {
                v.x += bias[col]; v.y += bias[col+1];
                v.z += bias[col+2]; v.w += bias[col+3];
            }
            *(float4*)(C + row * (size_t)N + col) = v;
        }
    }
}

// ----------------------------------------------------------------------------
// Flash attention, fp32. One CTA per (q-block of 64, head, batch).
// Q and K are stored TRANSPOSED in smem ([d][row], stride 68) so both
// S = Q K^T and O = P V run as sgemm-style loops with float4 smem loads.
// Online softmax over 16-lane groups via shfl_xor.
// ----------------------------------------------------------------------------
#define AST 68  // smem row stride (floats): 16B-aligned vectors, modest conflicts

__global__ __launch_bounds__(256) void attn_kernel(
    const float* __restrict__ Q, const float* __restrict__ KV,
    const float* __restrict__ mask, float* __restrict__ O)
{
    extern __shared__ float smem[];
    float* Qt = smem;              // [64 d][64 row]
    float* Kt = Qt + 64 * AST;     // [64 d][64 row]
    float* Vs = Kt + 64 * AST;     // [64 row][64 d]
    float* Pt = Vs + 64 * AST;     // [64 j][64 i]
    float* Ms = Pt + 64 * AST;     // [64] mask tile

    int qb = blockIdx.x, h = blockIdx.y, b = blockIdx.z;
    int tid = threadIdx.x;
    int tx = tid & 15, ty = tid >> 4;
    const float scale = 0.125f;    // 1/sqrt(64)

    // Load Q tile transposed, pre-scaled
    for (int i = tid; i < 64 * 16; i += 256) {
        int row = i >> 4, c4 = (i & 15) << 2;
        const float* gp = Q + (size_t)(b * TSEQ + qb * 64 + row) * DMM + h * DHD + c4;
        float4 v = *(const float4*)gp;
        Qt[(c4 + 0) * AST + row] = v.x * scale;
        Qt[(c4 + 1) * AST + row] = v.y * scale;
        Qt[(c4 + 2) * AST + row] = v.z * scale;
        Qt[(c4 + 3) * AST + row] = v.w * scale;
    }

    float acc[4][4] = {};
    float mrow[4], lrow[4];
    #pragma unroll
    for (int i = 0; i < 4; i++) { mrow[i] = -1e30f; lrow[i] = 0.f; }

    for (int kt = 0; kt < TSEQ / 64; kt++) {
        __syncthreads();  // previous PV done with Vs/Pt (also covers first Qt fill)
        // Load K transposed, V direct, mask tile
        for (int i = tid; i < 64 * 16; i += 256) {
            int row = i >> 4, c4 = (i & 15) << 2;
            const float* kp = KV + (size_t)(b * TSEQ + kt * 64 + row) * 2048 + h * 128 + c4;
            float4 k4 = *(const float4*)kp;
            Kt[(c4 + 0) * AST + row] = k4.x;
            Kt[(c4 + 1) * AST + row] = k4.y;
            Kt[(c4 + 2) * AST + row] = k4.z;
            Kt[(c4 + 3) * AST + row] = k4.w;
            *(float4*)&Vs[row * AST + c4] = *(const float4*)(kp + 64);
        }
        if (tid < 64) Ms[tid] = mask[b * TSEQ + kt * 64 + tid];
        __syncthreads();

        // S = Q K^T  (rows 4*ty.., cols 4*tx..)
        float s[4][4] = {};
        #pragma unroll 4
        for (int d = 0; d < 64; d++) {
            float4 ra = *(const float4*)&Qt[d * AST + ty * 4];
            float4 rb = *(const float4*)&Kt[d * AST + tx * 4];
            float raa[4] = {ra.x, ra.y, ra.z, ra.w};
            float rbb[4] = {rb.x, rb.y, rb.z, rb.w};
            #pragma unroll
            for (int i = 0; i < 4; i++)
                #pragma unroll
                for (int j = 0; j < 4; j++)
                    s[i][j] = fmaf(raa[i], rbb[j], s[i][j]);
        }
        // Mask (keys dimension)
        #pragma unroll
        for (int j = 0; j < 4; j++) {
            if (Ms[tx * 4 + j] == 0.f) {
                #pragma unroll
                for (int i = 0; i < 4; i++) s[i][j] = -1e30f;
            }
        }
        // Online softmax per row (reduce across the 16-lane tx group)
        #pragma unroll
        for (int i = 0; i < 4; i++) {
            float rm = fmaxf(fmaxf(s[i][0], s[i][1]), fmaxf(s[i][2], s[i][3]));
            #pragma unroll
            for (int o = 1; o < 16; o <<= 1)
                rm = fmaxf(rm, __shfl_xor_sync(0xffffffffu, rm, o));
            float mnew = fmaxf(mrow[i], rm);
            float corr = __expf(mrow[i] - mnew);
            float rs = 0.f;
            #pragma unroll
            for (int j = 0; j < 4; j++) { s[i][j] = __expf(s[i][j] - mnew); rs += s[i][j]; }
            #pragma unroll
            for (int o = 1; o < 16; o <<= 1)
                rs += __shfl_xor_sync(0xffffffffu, rs, o);
            lrow[i] = lrow[i] * corr + rs;
            mrow[i] = mnew;
            #pragma unroll
            for (int j = 0; j < 4; j++) acc[i][j] *= corr;
            #pragma unroll
            for (int j = 0; j < 4; j++)
                Pt[(tx * 4 + j) * AST + ty * 4 + i] = s[i][j];  // store P transposed
        }
        __syncthreads();

        // O += P V
        #pragma unroll 4
        for (int j = 0; j < 64; j++) {
            float4 pa = *(const float4*)&Pt[j * AST + ty * 4];
            float4 vb = *(const float4*)&Vs[j * AST + tx * 4];
            float paa[4] = {pa.x, pa.y, pa.z, pa.w};
            float vbb[4] = {vb.x, vb.y, vb.z, vb.w};
            #pragma unroll
            for (int i = 0; i < 4; i++)
                #pragma unroll
                for (int jj = 0; jj < 4; jj++)
                    acc[i][jj] = fmaf(paa[i], vbb[jj], acc[i][jj]);
        }
    }

    // Normalize and write [B*T, 1024] at head offset
    #pragma unroll
    for (int i = 0; i < 4; i++) {
        float inv = 1.f / lrow[i];
        size_t row = (size_t)(b * TSEQ + qb * 64 + ty * 4 + i);
        float4 v = make_float4(acc[i][0] * inv, acc[i][1] * inv,
                               acc[i][2] * inv, acc[i][3] * inv);
        *(float4*)(O + row * DMM + h * DHD + tx * 4) = v;
    }
}

// ----------------------------------------------------------------------------
extern "C" void kernel_launch(void* const* d_in, const int* in_sizes, int n_in,
                              void* d_out, int out_size)
{
    const float* x1   = (const float*)d_in[0];
    const float* x2   = (const float*)d_in[1];
    const float* mask = (const float*)d_in[2];
    const float* Wq   = (const float*)d_in[3];
    const float* Wkv  = (const float*)d_in[4];
    const float* Wo   = (const float*)d_in[5];
    const float* bo   = (const float*)d_in[6];
    float* out = (float*)d_out;

    float *q, *kv, *attn;
    cudaGetSymbolAddress((void**)&q, g_q);
    cudaGetSymbolAddress((void**)&kv, g_kv);
    cudaGetSymbolAddress((void**)&attn, g_attn);

    dim3 blk(256);
    // Q projection: [8192,1024] = x1 @ Wq
    sgemm_kernel<<<dim3(DMM / 128, BT / 128), blk>>>(x1, Wq, q, BT, DMM, DMM, nullptr);
    // KV projection: [8192,2048] = x2 @ Wkv
    sgemm_kernel<<<dim3(2 * DMM / 128, BT / 128), blk>>>(x2, Wkv, kv, BT, 2 * DMM, DMM, nullptr);

    // Flash attention
    int smem_bytes = (4 * 64 * AST + 64) * sizeof(float);  // ~70 KB
    cudaFuncSetAttribute(attn_kernel, cudaFuncAttributeMaxDynamicSharedMemorySize, smem_bytes);
    attn_kernel<<<dim3(TSEQ / 64, HN, BATCH), blk, smem_bytes>>>(q, kv, mask, attn);

    // Output projection + bias
    sgemm_kernel<<<dim3(DMM / 128, BT / 128), blk>>>(attn, Wo, out, BT, DMM, DMM, bo);
}

// round 3
// speedup vs baseline: 1.4030x; 1.4030x over previous
#include <cuda_runtime.h>

#define BT   8192   // B*T
#define DMM  1024
#define HN   16
#define DHD  64
#define TSEQ 2048
#define BATCH 4

// Scratch (allocation-free rule: __device__ globals)
__device__ float g_q[BT * DMM];        // Q projection  [8192,1024]
__device__ float g_kv[BT * 2 * DMM];   // KV projection [8192,2048]
__device__ float g_attn[BT * DMM];     // attention out [8192,1024]

// ----------------------------------------------------------------------------
// TF32 tensor-core GEMM: C[M,N] = A[M,K] @ B[K,N] (+bias), row-major fp32 I/O.
// mma.sync.aligned.m16n8k8.row.col.f32.tf32.tf32.f32
// CTA tile 128x128, BK=16, 256 threads = 8 warps, warp tile 64x32.
// Smem layouts give conflict-free fragment loads:
//   As [m][k], ld=20 : addr = g*20 + tig  -> all 32 banks distinct
//   Bs [k][n], ld=136: addr = tig*8 + g   -> all 32 banks distinct
// ----------------------------------------------------------------------------
#define LDA 20
#define LDB 136

__device__ __forceinline__ unsigned f2tf(float x) {
    unsigned r;
    asm("cvt.rna.tf32.f32 %0, %1;" : "=r"(r) : "f"(x));
    return r;
}

__device__ __forceinline__ void mma_tf32(float* d, const unsigned* a, const unsigned* b) {
    asm volatile(
        "mma.sync.aligned.m16n8k8.row.col.f32.tf32.tf32.f32 "
        "{%0,%1,%2,%3}, {%4,%5,%6,%7}, {%8,%9}, {%0,%1,%2,%3};\n"
        : "+f"(d[0]), "+f"(d[1]), "+f"(d[2]), "+f"(d[3])
        : "r"(a[0]), "r"(a[1]), "r"(a[2]), "r"(a[3]),
          "r"(b[0]), "r"(b[1]));
}

__global__ __launch_bounds__(256, 2) void tgemm_kernel(
    const float* __restrict__ A, const float* __restrict__ B,
    float* __restrict__ C, int M, int N, int K, const float* __restrict__ bias)
{
    __shared__ unsigned As[128 * LDA];   // 10.2 KB
    __shared__ unsigned Bs[16 * LDB];    //  8.7 KB
    int tid = threadIdx.x;
    int lane = tid & 31, wid = tid >> 5;
    int g = lane >> 2, tig = lane & 3;
    int warpM = wid & 1, warpN = wid >> 1;   // 2 x 4 warp grid

    const float* Ap = A + (size_t)blockIdx.y * 128 * K;
    const float* Bp = B + blockIdx.x * 128;

    float acc[4][4][4] = {};   // [mi][ni][frag]

    // Prefetch first tile (A: 128x16 = 512 vec4, B: 16x128 = 512 vec4; 2 each/thread)
    float4 pa[2], pb[2];
    #pragma unroll
    for (int i = 0; i < 2; i++) {
        int v = tid + i * 256;
        pa[i] = *(const float4*)(Ap + (size_t)(v >> 2) * K + (v & 3) * 4);
        pb[i] = *(const float4*)(Bp + (size_t)(v >> 5) * N + (v & 31) * 4);
    }

    for (int k0 = 0; k0 < K; k0 += 16) {
        // Store prefetched tile to smem with tf32 conversion
        #pragma unroll
        for (int i = 0; i < 2; i++) {
            int v = tid + i * 256;
            unsigned* da = &As[(v >> 2) * LDA + (v & 3) * 4];
            da[0] = f2tf(pa[i].x); da[1] = f2tf(pa[i].y);
            da[2] = f2tf(pa[i].z); da[3] = f2tf(pa[i].w);
            unsigned* db = &Bs[(v >> 5) * LDB + (v & 31) * 4];
            db[0] = f2tf(pb[i].x); db[1] = f2tf(pb[i].y);
            db[2] = f2tf(pb[i].z); db[3] = f2tf(pb[i].w);
        }
        __syncthreads();

        // Prefetch next tile (overlaps with compute below)
        if (k0 + 16 < K) {
            #pragma unroll
            for (int i = 0; i < 2; i++) {
                int v = tid + i * 256;
                pa[i] = *(const float4*)(Ap + (size_t)(v >> 2) * K + k0 + 16 + (v & 3) * 4);
                pb[i] = *(const float4*)(Bp + (size_t)(k0 + 16 + (v >> 5)) * N + (v & 31) * 4);
            }
        }

        // 2 k-steps of 8
        #pragma unroll
        for (int ks = 0; ks < 2; ks++) {
            int kk = ks * 8;
            unsigned af[4][4], bf[4][2];
            #pragma unroll
            for (int mi = 0; mi < 4; mi++) {
                int r = (warpM * 64 + mi * 16 + g) * LDA + kk + tig;
                af[mi][0] = As[r];
                af[mi][1] = As[r + 8 * LDA];
                af[mi][2] = As[r + 4];
                af[mi][3] = As[r + 8 * LDA + 4];
            }
            #pragma unroll
            for (int ni = 0; ni < 4; ni++) {
                int c = warpN * 32 + ni * 8 + g;
                bf[ni][0] = Bs[(kk + tig) * LDB + c];
                bf[ni][1] = Bs[(kk + tig + 4) * LDB + c];
            }
            #pragma unroll
            for (int mi = 0; mi < 4; mi++)
                #pragma unroll
                for (int ni = 0; ni < 4; ni++)
                    mma_tf32(acc[mi][ni], af[mi], bf[ni]);
        }
        __syncthreads();
    }

    // Epilogue: c0,c1 = (row g, cols tig*2, tig*2+1); c2,c3 = row g+8
    #pragma unroll
    for (int mi = 0; mi < 4; mi++) {
        size_t r0 = (size_t)blockIdx.y * 128 + warpM * 64 + mi * 16 + g;
        #pragma unroll
        for (int ni = 0; ni < 4; ni++) {
            int col = blockIdx.x * 128 + warpN * 32 + ni * 8 + tig * 2;
            float b0 = 0.f, b1 = 0.f;
            if (bias) { b0 = bias[col]; b1 = bias[col + 1]; }
            float2 v0 = make_float2(acc[mi][ni][0] + b0, acc[mi][ni][1] + b1);
            float2 v1 = make_float2(acc[mi][ni][2] + b0, acc[mi][ni][3] + b1);
            *(float2*)(C + r0 * N + col) = v0;
            *(float2*)(C + (r0 + 8) * N + col) = v1;
        }
    }
}

// ----------------------------------------------------------------------------
// Flash attention, fp32 (unchanged from R2 passing version).
// ----------------------------------------------------------------------------
#define AST 68

__global__ __launch_bounds__(256) void attn_kernel(
    const float* __restrict__ Q, const float* __restrict__ KV,
    const float* __restrict__ mask, float* __restrict__ O)
{
    extern __shared__ float smem[];
    float* Qt = smem;              // [64 d][64 row]
    float* Kt = Qt + 64 * AST;     // [64 d][64 row]
    float* Vs = Kt + 64 * AST;     // [64 row][64 d]
    float* Pt = Vs + 64 * AST;     // [64 j][64 i]
    float* Ms = Pt + 64 * AST;     // [64] mask tile

    int qb = blockIdx.x, h = blockIdx.y, b = blockIdx.z;
    int tid = threadIdx.x;
    int tx = tid & 15, ty = tid >> 4;
    const float scale = 0.125f;

    for (int i = tid; i < 64 * 16; i += 256) {
        int row = i >> 4, c4 = (i & 15) << 2;
        const float* gp = Q + (size_t)(b * TSEQ + qb * 64 + row) * DMM + h * DHD + c4;
        float4 v = *(const float4*)gp;
        Qt[(c4 + 0) * AST + row] = v.x * scale;
        Qt[(c4 + 1) * AST + row] = v.y * scale;
        Qt[(c4 + 2) * AST + row] = v.z * scale;
        Qt[(c4 + 3) * AST + row] = v.w * scale;
    }

    float acc[4][4] = {};
    float mrow[4], lrow[4];
    #pragma unroll
    for (int i = 0; i < 4; i++) { mrow[i] = -1e30f; lrow[i] = 0.f; }

    for (int kt = 0; kt < TSEQ / 64; kt++) {
        __syncthreads();
        for (int i = tid; i < 64 * 16; i += 256) {
            int row = i >> 4, c4 = (i & 15) << 2;
            const float* kp = KV + (size_t)(b * TSEQ + kt * 64 + row) * 2048 + h * 128 + c4;
            float4 k4 = *(const float4*)kp;
            Kt[(c4 + 0) * AST + row] = k4.x;
            Kt[(c4 + 1) * AST + row] = k4.y;
            Kt[(c4 + 2) * AST + row] = k4.z;
            Kt[(c4 + 3) * AST + row] = k4.w;
            *(float4*)&Vs[row * AST + c4] = *(const float4*)(kp + 64);
        }
        if (tid < 64) Ms[tid] = mask[b * TSEQ + kt * 64 + tid];
        __syncthreads();

        float s[4][4] = {};
        #pragma unroll 4
        for (int d = 0; d < 64; d++) {
            float4 ra = *(const float4*)&Qt[d * AST + ty * 4];
            float4 rb = *(const float4*)&Kt[d * AST + tx * 4];
            float raa[4] = {ra.x, ra.y, ra.z, ra.w};
            float rbb[4] = {rb.x, rb.y, rb.z, rb.w};
            #pragma unroll
            for (int i = 0; i < 4; i++)
                #pragma unroll
                for (int j = 0; j < 4; j++)
                    s[i][j] = fmaf(raa[i], rbb[j], s[i][j]);
        }
        #pragma unroll
        for (int j = 0; j < 4; j++) {
            if (Ms[tx * 4 + j] == 0.f) {
                #pragma unroll
                for (int i = 0; i < 4; i++) s[i][j] = -1e30f;
            }
        }
        #pragma unroll
        for (int i = 0; i < 4; i++) {
            float rm = fmaxf(fmaxf(s[i][0], s[i][1]), fmaxf(s[i][2], s[i][3]));
            #pragma unroll
            for (int o = 1; o < 16; o <<= 1)
                rm = fmaxf(rm, __shfl_xor_sync(0xffffffffu, rm, o));
            float mnew = fmaxf(mrow[i], rm);
            float corr = __expf(mrow[i] - mnew);
            float rs = 0.f;
            #pragma unroll
            for (int j = 0; j < 4; j++) { s[i][j] = __expf(s[i][j] - mnew); rs += s[i][j]; }
            #pragma unroll
            for (int o = 1; o < 16; o <<= 1)
                rs += __shfl_xor_sync(0xffffffffu, rs, o);
            lrow[i] = lrow[i] * corr + rs;
            mrow[i] = mnew;
            #pragma unroll
            for (int j = 0; j < 4; j++) acc[i][j] *= corr;
            #pragma unroll
            for (int j = 0; j < 4; j++)
                Pt[(tx * 4 + j) * AST + ty * 4 + i] = s[i][j];
        }
        __syncthreads();

        #pragma unroll 4
        for (int j = 0; j < 64; j++) {
            float4 pa = *(const float4*)&Pt[j * AST + ty * 4];
            float4 vb = *(const float4*)&Vs[j * AST + tx * 4];
            float paa[4] = {pa.x, pa.y, pa.z, pa.w};
            float vbb[4] = {vb.x, vb.y, vb.z, vb.w};
            #pragma unroll
            for (int i = 0; i < 4; i++)
                #pragma unroll
                for (int jj = 0; jj < 4; jj++)
                    acc[i][jj] = fmaf(paa[i], vbb[jj], acc[i][jj]);
        }
    }

    #pragma unroll
    for (int i = 0; i < 4; i++) {
        float inv = 1.f / lrow[i];
        size_t row = (size_t)(b * TSEQ + qb * 64 + ty * 4 + i);
        float4 v = make_float4(acc[i][0] * inv, acc[i][1] * inv,
                               acc[i][2] * inv, acc[i][3] * inv);
        *(float4*)(O + row * DMM + h * DHD + tx * 4) = v;
    }
}

// ----------------------------------------------------------------------------
extern "C" void kernel_launch(void* const* d_in, const int* in_sizes, int n_in,
                              void* d_out, int out_size)
{
    const float* x1   = (const float*)d_in[0];
    const float* x2   = (const float*)d_in[1];
    const float* mask = (const float*)d_in[2];
    const float* Wq   = (const float*)d_in[3];
    const float* Wkv  = (const float*)d_in[4];
    const float* Wo   = (const float*)d_in[5];
    const float* bo   = (const float*)d_in[6];
    float* out = (float*)d_out;

    float *q, *kv, *attn;
    cudaGetSymbolAddress((void**)&q, g_q);
    cudaGetSymbolAddress((void**)&kv, g_kv);
    cudaGetSymbolAddress((void**)&attn, g_attn);

    dim3 blk(256);
    // Q projection: [8192,1024] = x1 @ Wq
    tgemm_kernel<<<dim3(DMM / 128, BT / 128), blk>>>(x1, Wq, q, BT, DMM, DMM, nullptr);
    // KV projection: [8192,2048] = x2 @ Wkv
    tgemm_kernel<<<dim3(2 * DMM / 128, BT / 128), blk>>>(x2, Wkv, kv, BT, 2 * DMM, DMM, nullptr);

    // Flash attention (fp32 SIMT)
    int smem_bytes = (4 * 64 * AST + 64) * sizeof(float);
    cudaFuncSetAttribute(attn_kernel, cudaFuncAttributeMaxDynamicSharedMemorySize, smem_bytes);
    attn_kernel<<<dim3(TSEQ / 64, HN, BATCH), blk, smem_bytes>>>(q, kv, mask, attn);

    // Output projection + bias
    tgemm_kernel<<<dim3(DMM / 128, BT / 128), blk>>>(attn, Wo, out, BT, DMM, DMM, bo);
}

// round 5
// speedup vs baseline: 3.0227x; 2.1545x over previous
#include <cuda_runtime.h>

#define BT   8192   // B*T
#define DMM  1024
#define HN   16
#define DHD  64
#define TSEQ 2048
#define BATCH 4

// Scratch (allocation-free rule: __device__ globals)
__device__ float g_q[BT * DMM];        // Q projection  [8192,1024]
__device__ float g_kv[BT * 2 * DMM];   // KV projection [8192,2048]
__device__ float g_attn[BT * DMM];     // attention out [8192,1024]

__device__ __forceinline__ unsigned f2tf(float x) {
    unsigned r;
    asm("cvt.rna.tf32.f32 %0, %1;" : "=r"(r) : "f"(x));
    return r;
}

__device__ __forceinline__ void mma_tf32(float* d, const unsigned* a, const unsigned* b) {
    asm volatile(
        "mma.sync.aligned.m16n8k8.row.col.f32.tf32.tf32.f32 "
        "{%0,%1,%2,%3}, {%4,%5,%6,%7}, {%8,%9}, {%0,%1,%2,%3};\n"
        : "+f"(d[0]), "+f"(d[1]), "+f"(d[2]), "+f"(d[3])
        : "r"(a[0]), "r"(a[1]), "r"(a[2]), "r"(a[3]),
          "r"(b[0]), "r"(b[1]));
}

// ----------------------------------------------------------------------------
// TF32 tensor-core GEMM (unchanged from R3 passing version).
// ----------------------------------------------------------------------------
#define LDA 20
#define LDB 136

__global__ __launch_bounds__(256, 2) void tgemm_kernel(
    const float* __restrict__ A, const float* __restrict__ B,
    float* __restrict__ C, int M, int N, int K, const float* __restrict__ bias)
{
    __shared__ unsigned As[128 * LDA];
    __shared__ unsigned Bs[16 * LDB];
    int tid = threadIdx.x;
    int lane = tid & 31, wid = tid >> 5;
    int g = lane >> 2, tig = lane & 3;
    int warpM = wid & 1, warpN = wid >> 1;

    const float* Ap = A + (size_t)blockIdx.y * 128 * K;
    const float* Bp = B + blockIdx.x * 128;

    float acc[4][4][4] = {};

    float4 pa[2], pb[2];
    #pragma unroll
    for (int i = 0; i < 2; i++) {
        int v = tid + i * 256;
        pa[i] = *(const float4*)(Ap + (size_t)(v >> 2) * K + (v & 3) * 4);
        pb[i] = *(const float4*)(Bp + (size_t)(v >> 5) * N + (v & 31) * 4);
    }

    for (int k0 = 0; k0 < K; k0 += 16) {
        #pragma unroll
        for (int i = 0; i < 2; i++) {
            int v = tid + i * 256;
            unsigned* da = &As[(v >> 2) * LDA + (v & 3) * 4];
            da[0] = f2tf(pa[i].x); da[1] = f2tf(pa[i].y);
            da[2] = f2tf(pa[i].z); da[3] = f2tf(pa[i].w);
            unsigned* db = &Bs[(v >> 5) * LDB + (v & 31) * 4];
            db[0] = f2tf(pb[i].x); db[1] = f2tf(pb[i].y);
            db[2] = f2tf(pb[i].z); db[3] = f2tf(pb[i].w);
        }
        __syncthreads();

        if (k0 + 16 < K) {
            #pragma unroll
            for (int i = 0; i < 2; i++) {
                int v = tid + i * 256;
                pa[i] = *(const float4*)(Ap + (size_t)(v >> 2) * K + k0 + 16 + (v & 3) * 4);
                pb[i] = *(const float4*)(Bp + (size_t)(k0 + 16 + (v >> 5)) * N + (v & 31) * 4);
            }
        }

        #pragma unroll
        for (int ks = 0; ks < 2; ks++) {
            int kk = ks * 8;
            unsigned af[4][4], bf[4][2];
            #pragma unroll
            for (int mi = 0; mi < 4; mi++) {
                int r = (warpM * 64 + mi * 16 + g) * LDA + kk + tig;
                af[mi][0] = As[r];
                af[mi][1] = As[r + 8 * LDA];
                af[mi][2] = As[r + 4];
                af[mi][3] = As[r + 8 * LDA + 4];
            }
            #pragma unroll
            for (int ni = 0; ni < 4; ni++) {
                int c = warpN * 32 + ni * 8 + g;
                bf[ni][0] = Bs[(kk + tig) * LDB + c];
                bf[ni][1] = Bs[(kk + tig + 4) * LDB + c];
            }
            #pragma unroll
            for (int mi = 0; mi < 4; mi++)
                #pragma unroll
                for (int ni = 0; ni < 4; ni++)
                    mma_tf32(acc[mi][ni], af[mi], bf[ni]);
        }
        __syncthreads();
    }

    #pragma unroll
    for (int mi = 0; mi < 4; mi++) {
        size_t r0 = (size_t)blockIdx.y * 128 + warpM * 64 + mi * 16 + g;
        #pragma unroll
        for (int ni = 0; ni < 4; ni++) {
            int col = blockIdx.x * 128 + warpN * 32 + ni * 8 + tig * 2;
            float b0 = 0.f, b1 = 0.f;
            if (bias) { b0 = bias[col]; b1 = bias[col + 1]; }
            float2 v0 = make_float2(acc[mi][ni][0] + b0, acc[mi][ni][1] + b1);
            float2 v1 = make_float2(acc[mi][ni][2] + b0, acc[mi][ni][3] + b1);
            *(float2*)(C + r0 * N + col) = v0;
            *(float2*)(C + (r0 + 8) * N + col) = v1;
        }
    }
}

// ----------------------------------------------------------------------------
// Flash attention on tensor cores (tf32 mma.m16n8k8).
// CTA: 128 queries x (head, batch). 256 threads = 8 warps, warp owns 16 rows.
// Layouts (all conflict-free for their fragment pattern):
//   Qs [row][d]   stride 68 (A-frag:  4g+tig mod 32 distinct)
//   Ks [key][d]   stride 68 (B-frag:  4g+tig distinct)
//   Vs [key][d]   stride 72 (B-frag:  8tig+g distinct)
//   Ps [row][key] stride 68 (A-frag)
// ----------------------------------------------------------------------------
#define BQ 128
#define BK 64
#define LQ 68
#define LK 68
#define LV 72
#define LP 68

__global__ __launch_bounds__(256, 1) void fattn_kernel(
    const float* __restrict__ Q, const float* __restrict__ KV,
    const float* __restrict__ mask, float* __restrict__ O)
{
    extern __shared__ unsigned sm[];
    unsigned* Qs = sm;                     // [128][LQ]
    unsigned* Ks = Qs + BQ * LQ;           // [64][LK]
    unsigned* Vs = Ks + BK * LK;           // [64][LV]
    unsigned* Ps = Vs + BK * LV;           // [128][LP]
    float*    Msk = (float*)(Ps + BQ * LP); // [64]

    int qb = blockIdx.x, h = blockIdx.y, b = blockIdx.z;
    int tid = threadIdx.x;
    int lane = tid & 31, wid = tid >> 5;
    int g = lane >> 2, tig = lane & 3;
    int warpRow = wid * 16;
    const float scale = 0.125f;

    // Load Q tile (pre-scaled, tf32)
    for (int i = tid; i < BQ * 16; i += 256) {
        int row = i >> 4, c4 = (i & 15) << 2;
        const float* gp = Q + (size_t)(b * TSEQ + qb * BQ + row) * DMM + h * DHD + c4;
        float4 v = *(const float4*)gp;
        unsigned* d = &Qs[row * LQ + c4];
        d[0] = f2tf(v.x * scale); d[1] = f2tf(v.y * scale);
        d[2] = f2tf(v.z * scale); d[3] = f2tf(v.w * scale);
    }

    float acc[8][4] = {};
    float m0 = -1e30f, m1 = -1e30f, l0 = 0.f, l1 = 0.f;

    for (int kt = 0; kt < TSEQ / BK; kt++) {
        __syncthreads();   // prev PV done with Vs; Q load done (first iter)
        // Load K,V tile (tf32)
        for (int i = tid; i < BK * 16; i += 256) {
            int row = i >> 4, c4 = (i & 15) << 2;
            const float* kp = KV + (size_t)(b * TSEQ + kt * BK + row) * 2048 + h * 128 + c4;
            float4 k4 = *(const float4*)kp;
            float4 v4 = *(const float4*)(kp + 64);
            unsigned* dk = &Ks[row * LK + c4];
            dk[0] = f2tf(k4.x); dk[1] = f2tf(k4.y);
            dk[2] = f2tf(k4.z); dk[3] = f2tf(k4.w);
            unsigned* dv = &Vs[row * LV + c4];
            dv[0] = f2tf(v4.x); dv[1] = f2tf(v4.y);
            dv[2] = f2tf(v4.z); dv[3] = f2tf(v4.w);
        }
        if (tid < BK) Msk[tid] = mask[b * TSEQ + kt * BK + tid];
        __syncthreads();

        // S = Q K^T  (per warp: 16 x 64)
        float s[8][4] = {};
        #pragma unroll
        for (int ks = 0; ks < 8; ks++) {
            int kk = ks * 8;
            unsigned af[4];
            int r = (warpRow + g) * LQ + kk + tig;
            af[0] = Qs[r];
            af[1] = Qs[r + 8 * LQ];
            af[2] = Qs[r + 4];
            af[3] = Qs[r + 8 * LQ + 4];
            #pragma unroll
            for (int nt = 0; nt < 8; nt++) {
                unsigned bf[2];
                int c = nt * 8 + g;
                bf[0] = Ks[c * LK + kk + tig];
                bf[1] = Ks[c * LK + kk + tig + 4];
                mma_tf32(s[nt], af, bf);
            }
        }

        // Mask (key cols 2*tig, 2*tig+1 within each n-tile)
        #pragma unroll
        for (int nt = 0; nt < 8; nt++) {
            int c0 = nt * 8 + tig * 2;
            if (Msk[c0] == 0.f)     { s[nt][0] = -1e30f; s[nt][2] = -1e30f; }
            if (Msk[c0 + 1] == 0.f) { s[nt][1] = -1e30f; s[nt][3] = -1e30f; }
        }

        // Online softmax: thread owns rows (warpRow+g) and (+8); reduce over tig (xor 1,2)
        float mx0 = -1e30f, mx1 = -1e30f;
        #pragma unroll
        for (int nt = 0; nt < 8; nt++) {
            mx0 = fmaxf(mx0, fmaxf(s[nt][0], s[nt][1]));
            mx1 = fmaxf(mx1, fmaxf(s[nt][2], s[nt][3]));
        }
        #pragma unroll
        for (int o = 1; o < 4; o <<= 1) {
            mx0 = fmaxf(mx0, __shfl_xor_sync(0xffffffffu, mx0, o));
            mx1 = fmaxf(mx1, __shfl_xor_sync(0xffffffffu, mx1, o));
        }
        float mn0 = fmaxf(m0, mx0), mn1 = fmaxf(m1, mx1);
        float cr0 = __expf(m0 - mn0), cr1 = __expf(m1 - mn1);
        float rs0 = 0.f, rs1 = 0.f;
        #pragma unroll
        for (int nt = 0; nt < 8; nt++) {
            s[nt][0] = __expf(s[nt][0] - mn0); rs0 += s[nt][0];
            s[nt][1] = __expf(s[nt][1] - mn0); rs0 += s[nt][1];
            s[nt][2] = __expf(s[nt][2] - mn1); rs1 += s[nt][2];
            s[nt][3] = __expf(s[nt][3] - mn1); rs1 += s[nt][3];
        }
        #pragma unroll
        for (int o = 1; o < 4; o <<= 1) {
            rs0 += __shfl_xor_sync(0xffffffffu, rs0, o);
            rs1 += __shfl_xor_sync(0xffffffffu, rs1, o);
        }
        l0 = l0 * cr0 + rs0;  m0 = mn0;
        l1 = l1 * cr1 + rs1;  m1 = mn1;
        #pragma unroll
        for (int nt = 0; nt < 8; nt++) {
            acc[nt][0] *= cr0; acc[nt][1] *= cr0;
            acc[nt][2] *= cr1; acc[nt][3] *= cr1;
        }

        // Store P (tf32) — warp-private rows, so only __syncwarp needed
        #pragma unroll
        for (int nt = 0; nt < 8; nt++) {
            int colb = nt * 8 + tig * 2;
            int r0 = (warpRow + g) * LP + colb;
            int r1 = (warpRow + g + 8) * LP + colb;
            Ps[r0] = f2tf(s[nt][0]); Ps[r0 + 1] = f2tf(s[nt][1]);
            Ps[r1] = f2tf(s[nt][2]); Ps[r1 + 1] = f2tf(s[nt][3]);
        }
        __syncwarp();

        // O += P V  (per warp: 16 x 64, k over 64 keys)
        #pragma unroll
        for (int ks = 0; ks < 8; ks++) {
            int kk = ks * 8;
            unsigned af[4];
            int r = (warpRow + g) * LP + kk + tig;
            af[0] = Ps[r];
            af[1] = Ps[r + 8 * LP];
            af[2] = Ps[r + 4];
            af[3] = Ps[r + 8 * LP + 4];
            #pragma unroll
            for (int nt = 0; nt < 8; nt++) {
                unsigned bf[2];
                int c = nt * 8 + g;
                bf[0] = Vs[(kk + tig) * LV + c];
                bf[1] = Vs[(kk + tig + 4) * LV + c];
                mma_tf32(acc[nt], af, bf);
            }
        }
    }

    // Epilogue: normalize, write to [B*T, 1024] at head offset
    float inv0 = 1.f / l0, inv1 = 1.f / l1;
    size_t row0 = (size_t)(b * TSEQ + qb * BQ + warpRow + g);
    #pragma unroll
    for (int nt = 0; nt < 8; nt++) {
        int col = h * DHD + nt * 8 + tig * 2;
        *(float2*)(O + row0 * DMM + col) =
            make_float2(acc[nt][0] * inv0, acc[nt][1] * inv0);
        *(float2*)(O + (row0 + 8) * DMM + col) =
            make_float2(acc[nt][2] * inv1, acc[nt][3] * inv1);
    }
}

// ----------------------------------------------------------------------------
extern "C" void kernel_launch(void* const* d_in, const int* in_sizes, int n_in,
                              void* d_out, int out_size)
{
    const float* x1   = (const float*)d_in[0];
    const float* x2   = (const float*)d_in[1];
    const float* mask = (const float*)d_in[2];
    const float* Wq   = (const float*)d_in[3];
    const float* Wkv  = (const float*)d_in[4];
    const float* Wo   = (const float*)d_in[5];
    const float* bo   = (const float*)d_in[6];
    float* out = (float*)d_out;

    float *q, *kv, *attn;
    cudaGetSymbolAddress((void**)&q, g_q);
    cudaGetSymbolAddress((void**)&kv, g_kv);
    cudaGetSymbolAddress((void**)&attn, g_attn);

    dim3 blk(256);
    tgemm_kernel<<<dim3(DMM / 128, BT / 128), blk>>>(x1, Wq, q, BT, DMM, DMM, nullptr);
    tgemm_kernel<<<dim3(2 * DMM / 128, BT / 128), blk>>>(x2, Wkv, kv, BT, 2 * DMM, DMM, nullptr);

    int smem_bytes = (BQ * LQ + BK * LK + BK * LV + BQ * LP + BK) * sizeof(unsigned);
    cudaFuncSetAttribute(fattn_kernel, cudaFuncAttributeMaxDynamicSharedMemorySize, smem_bytes);
    fattn_kernel<<<dim3(TSEQ / BQ, HN, BATCH), blk, smem_bytes>>>(q, kv, mask, attn);

    tgemm_kernel<<<dim3(DMM / 128, BT / 128), blk>>>(attn, Wo, out, BT, DMM, DMM, bo);
}

// round 9
// speedup vs baseline: 3.5833x; 1.1854x over previous
#include <cuda_runtime.h>

#define BT   8192   // B*T
#define DMM  1024
#define HN   16
#define DHD  64
#define TSEQ 2048
#define BATCH 4

__device__ float g_q[BT * DMM];        // Q proj, stored as RNA-tf32 bits, pre-scaled
__device__ float g_kv[BT * 2 * DMM];   // KV proj, stored as RNA-tf32 bits
__device__ float g_attn[BT * DMM];     // attention out, full fp32

__device__ __forceinline__ void cp16(unsigned* smem, const float* gmem) {
    unsigned s = (unsigned)__cvta_generic_to_shared(smem);
    asm volatile("cp.async.cg.shared.global [%0], [%1], 16;\n" :: "r"(s), "l"(gmem));
}
__device__ __forceinline__ void cp_commit() {
    asm volatile("cp.async.commit_group;\n" ::: "memory");
}
__device__ __forceinline__ void cp_wait1() {
    asm volatile("cp.async.wait_group 1;\n" ::: "memory");
}
__device__ __forceinline__ void cp_wait0() {
    asm volatile("cp.async.wait_group 0;\n" ::: "memory");
}

__device__ __forceinline__ unsigned f2tf(float x) {   // RNA round to tf32
    unsigned r;
    asm("cvt.rna.tf32.f32 %0, %1;" : "=r"(r) : "f"(x));
    return r;
}
__device__ __forceinline__ unsigned u2tf(unsigned x) { // RNA on raw bits
    unsigned r;
    asm("cvt.rna.tf32.f32 %0, %1;" : "=r"(r) : "f"(__uint_as_float(x)));
    return r;
}

__device__ __forceinline__ void mma_tf32(float* d, const unsigned* a, const unsigned* b) {
    asm volatile(
        "mma.sync.aligned.m16n8k8.row.col.f32.tf32.tf32.f32 "
        "{%0,%1,%2,%3}, {%4,%5,%6,%7}, {%8,%9}, {%0,%1,%2,%3};\n"
        : "+f"(d[0]), "+f"(d[1]), "+f"(d[2]), "+f"(d[3])
        : "r"(a[0]), "r"(a[1]), "r"(a[2]), "r"(a[3]),
          "r"(b[0]), "r"(b[1]));
}

// ----------------------------------------------------------------------------
// TF32 GEMM, cp.async double-buffered, RNA conversion on fragments after LDS.
// CTA 128x128, BK=16, 8 warps (2x4), warp tile 64x32.
// convert=1: epilogue stores RNA-tf32 bit patterns of (acc * oscale).
// convert=0: epilogue stores full fp32 acc (+bias).
// ----------------------------------------------------------------------------
#define LDA 20
#define LDB 136

__global__ __launch_bounds__(256, 2) void tgemm_kernel(
    const float* __restrict__ A, const float* __restrict__ B,
    float* __restrict__ C, int M, int N, int K, const float* __restrict__ bias,
    float oscale, int convert)
{
    __shared__ unsigned As[2][128 * LDA];
    __shared__ unsigned Bs[2][16 * LDB];
    int tid = threadIdx.x;
    int lane = tid & 31, wid = tid >> 5;
    int g = lane >> 2, tig = lane & 3;
    int warpM = wid & 1, warpN = wid >> 1;

    const float* Ap = A + (size_t)blockIdx.y * 128 * K;
    const float* Bp = B + blockIdx.x * 128;

    float acc[4][4][4] = {};
    int av0 = tid, av1 = tid + 256;

    auto issueTile = [&](int k0, int st) {
        cp16(&As[st][(av0 >> 2) * LDA + (av0 & 3) * 4],
             Ap + (size_t)(av0 >> 2) * K + k0 + (av0 & 3) * 4);
        cp16(&As[st][(av1 >> 2) * LDA + (av1 & 3) * 4],
             Ap + (size_t)(av1 >> 2) * K + k0 + (av1 & 3) * 4);
        cp16(&Bs[st][(av0 >> 5) * LDB + (av0 & 31) * 4],
             Bp + (size_t)(k0 + (av0 >> 5)) * N + (av0 & 31) * 4);
        cp16(&Bs[st][(av1 >> 5) * LDB + (av1 & 31) * 4],
             Bp + (size_t)(k0 + (av1 >> 5)) * N + (av1 & 31) * 4);
        cp_commit();
    };

    int NIT = K >> 4;
    issueTile(0, 0);

    for (int it = 0; it < NIT; it++) {
        int st = it & 1;
        if (it + 1 < NIT) { issueTile((it + 1) << 4, st ^ 1); cp_wait1(); }
        else              { cp_wait0(); }
        __syncthreads();

        #pragma unroll
        for (int ks = 0; ks < 2; ks++) {
            int kk = ks * 8;
            unsigned af[4][4], bf[4][2];
            #pragma unroll
            for (int mi = 0; mi < 4; mi++) {
                int r = (warpM * 64 + mi * 16 + g) * LDA + kk + tig;
                af[mi][0] = u2tf(As[st][r]);
                af[mi][1] = u2tf(As[st][r + 8 * LDA]);
                af[mi][2] = u2tf(As[st][r + 4]);
                af[mi][3] = u2tf(As[st][r + 8 * LDA + 4]);
            }
            #pragma unroll
            for (int ni = 0; ni < 4; ni++) {
                int c = warpN * 32 + ni * 8 + g;
                bf[ni][0] = u2tf(Bs[st][(kk + tig) * LDB + c]);
                bf[ni][1] = u2tf(Bs[st][(kk + tig + 4) * LDB + c]);
            }
            #pragma unroll
            for (int mi = 0; mi < 4; mi++)
                #pragma unroll
                for (int ni = 0; ni < 4; ni++)
                    mma_tf32(acc[mi][ni], af[mi], bf[ni]);
        }
        __syncthreads();
    }

    #pragma unroll
    for (int mi = 0; mi < 4; mi++) {
        size_t r0 = (size_t)blockIdx.y * 128 + warpM * 64 + mi * 16 + g;
        #pragma unroll
        for (int ni = 0; ni < 4; ni++) {
            int col = blockIdx.x * 128 + warpN * 32 + ni * 8 + tig * 2;
            if (convert) {
                // store RNA-tf32 bit patterns (consumed raw by fattn cp.async)
                uint2 v0 = make_uint2(f2tf(acc[mi][ni][0] * oscale),
                                      f2tf(acc[mi][ni][1] * oscale));
                uint2 v1 = make_uint2(f2tf(acc[mi][ni][2] * oscale),
                                      f2tf(acc[mi][ni][3] * oscale));
                *(uint2*)((unsigned*)C + r0 * N + col) = v0;
                *(uint2*)((unsigned*)C + (r0 + 8) * N + col) = v1;
            } else {
                float b0 = 0.f, b1 = 0.f;
                if (bias) { b0 = bias[col]; b1 = bias[col + 1]; }
                *(float2*)(C + r0 * N + col) =
                    make_float2(acc[mi][ni][0] + b0, acc[mi][ni][1] + b1);
                *(float2*)(C + (r0 + 8) * N + col) =
                    make_float2(acc[mi][ni][2] + b0, acc[mi][ni][3] + b1);
            }
        }
    }
}

// ----------------------------------------------------------------------------
// Flash attention, tf32 MMA. Q/K/V arrive as pre-converted RNA-tf32 bits
// (Q pre-scaled by 1/8), loaded purely via cp.async double-buffering.
//   Qs [row][d]   ld=68   Ks [key][d] ld=68
//   Vs [key][d]   ld=72   Ps [row][key] ld=68     (all conflict-free)
// ----------------------------------------------------------------------------
#define BQ 128
#define BK 64
#define LQ 68
#define LK 68
#define LV 72
#define LP 68

__global__ __launch_bounds__(256, 1) void fattn_kernel(
    const float* __restrict__ Q, const float* __restrict__ KV,
    const float* __restrict__ mask, float* __restrict__ O)
{
    extern __shared__ unsigned sm[];
    unsigned* Qs = sm;                          // [128][68]
    unsigned* Ps = Qs + BQ * LQ;                // [128][68]
    unsigned* Ks = Ps + BQ * LP;                // [2][64][68]
    unsigned* Vs = Ks + 2 * BK * LK;            // [2][64][72]
    float*    Msk = (float*)(Vs + 2 * BK * LV); // [2048]

    int qb = blockIdx.x, h = blockIdx.y, b = blockIdx.z;
    int tid = threadIdx.x;
    int lane = tid & 31, wid = tid >> 5;
    int g = lane >> 2, tig = lane & 3;
    int warpRow = wid * 16;

    const float* KVbase = KV + (size_t)b * TSEQ * 2048 + h * 128;

    auto issueKV = [&](int kt, int st) {
        unsigned* Kst = Ks + st * BK * LK;
        unsigned* Vst = Vs + st * BK * LV;
        const float* base = KVbase + (size_t)kt * BK * 2048;
        #pragma unroll
        for (int i2 = 0; i2 < 4; i2++) {
            int i = tid + i2 * 256;
            int row = i >> 4, c4 = (i & 15) << 2;
            const float* kp = base + (size_t)row * 2048 + c4;
            cp16(&Kst[row * LK + c4], kp);
            cp16(&Vst[row * LV + c4], kp + 64);
        }
        cp_commit();
    };

    // Q tile (already scaled RNA-tf32 bits) + mask row, all via cp.async;
    // joins the first commit group together with KV tile 0.
    {
        const float* Qbase = Q + (size_t)(b * TSEQ + qb * BQ) * DMM + h * DHD;
        #pragma unroll
        for (int i2 = 0; i2 < 8; i2++) {
            int i = tid + i2 * 256;
            int row = i >> 4, c4 = (i & 15) << 2;
            cp16(&Qs[row * LQ + c4], Qbase + (size_t)row * DMM + c4);
        }
        #pragma unroll
        for (int i2 = 0; i2 < 2; i2++) {
            int i = tid + i2 * 256;
            cp16((unsigned*)&Msk[i * 4], mask + (size_t)b * TSEQ + i * 4);
        }
    }
    issueKV(0, 0);   // commit group: Q + mask + KV0

    float acc[8][4] = {};
    float m0 = -1e30f, m1 = -1e30f, l0 = 0.f, l1 = 0.f;
    const int NT = TSEQ / BK;

    for (int kt = 0; kt < NT; kt++) {
        int st = kt & 1;
        if (kt + 1 < NT) { issueKV(kt + 1, st ^ 1); cp_wait1(); }
        else             { cp_wait0(); }
        __syncthreads();

        unsigned* Kst = Ks + st * BK * LK;
        unsigned* Vst = Vs + st * BK * LV;

        // S = Q K^T (warp: 16 x 64)
        float s[8][4] = {};
        #pragma unroll
        for (int ks = 0; ks < 8; ks++) {
            int kk = ks * 8;
            unsigned af[4];
            int r = (warpRow + g) * LQ + kk + tig;
            af[0] = Qs[r];
            af[1] = Qs[r + 8 * LQ];
            af[2] = Qs[r + 4];
            af[3] = Qs[r + 8 * LQ + 4];
            #pragma unroll
            for (int nt = 0; nt < 8; nt++) {
                unsigned bf[2];
                int c = nt * 8 + g;
                bf[0] = Kst[c * LK + kk + tig];
                bf[1] = Kst[c * LK + kk + tig + 4];
                mma_tf32(s[nt], af, bf);
            }
        }

        // Mask
        #pragma unroll
        for (int nt = 0; nt < 8; nt++) {
            int c0 = kt * BK + nt * 8 + tig * 2;
            if (Msk[c0] == 0.f)     { s[nt][0] = -1e30f; s[nt][2] = -1e30f; }
            if (Msk[c0 + 1] == 0.f) { s[nt][1] = -1e30f; s[nt][3] = -1e30f; }
        }

        // Online softmax (thread rows warpRow+g and +8; reduce over tig)
        float mx0 = -1e30f, mx1 = -1e30f;
        #pragma unroll
        for (int nt = 0; nt < 8; nt++) {
            mx0 = fmaxf(mx0, fmaxf(s[nt][0], s[nt][1]));
            mx1 = fmaxf(mx1, fmaxf(s[nt][2], s[nt][3]));
        }
        #pragma unroll
        for (int o = 1; o < 4; o <<= 1) {
            mx0 = fmaxf(mx0, __shfl_xor_sync(0xffffffffu, mx0, o));
            mx1 = fmaxf(mx1, __shfl_xor_sync(0xffffffffu, mx1, o));
        }
        float mn0 = fmaxf(m0, mx0), mn1 = fmaxf(m1, mx1);
        float cr0 = __expf(m0 - mn0), cr1 = __expf(m1 - mn1);
        float rs0 = 0.f, rs1 = 0.f;
        #pragma unroll
        for (int nt = 0; nt < 8; nt++) {
            s[nt][0] = __expf(s[nt][0] - mn0); rs0 += s[nt][0];
            s[nt][1] = __expf(s[nt][1] - mn0); rs0 += s[nt][1];
            s[nt][2] = __expf(s[nt][2] - mn1); rs1 += s[nt][2];
            s[nt][3] = __expf(s[nt][3] - mn1); rs1 += s[nt][3];
        }
        #pragma unroll
        for (int o = 1; o < 4; o <<= 1) {
            rs0 += __shfl_xor_sync(0xffffffffu, rs0, o);
            rs1 += __shfl_xor_sync(0xffffffffu, rs1, o);
        }
        l0 = l0 * cr0 + rs0;  m0 = mn0;
        l1 = l1 * cr1 + rs1;  m1 = mn1;
        #pragma unroll
        for (int nt = 0; nt < 8; nt++) {
            acc[nt][0] *= cr0; acc[nt][1] *= cr0;
            acc[nt][2] *= cr1; acc[nt][3] *= cr1;
        }

        // P -> smem, RNA-tf32; warp-private rows
        #pragma unroll
        for (int nt = 0; nt < 8; nt++) {
            int colb = nt * 8 + tig * 2;
            int r0 = (warpRow + g) * LP + colb;
            int r1 = (warpRow + g + 8) * LP + colb;
            Ps[r0] = f2tf(s[nt][0]); Ps[r0 + 1] = f2tf(s[nt][1]);
            Ps[r1] = f2tf(s[nt][2]); Ps[r1 + 1] = f2tf(s[nt][3]);
        }
        __syncwarp();

        // O += P V
        #pragma unroll
        for (int ks = 0; ks < 8; ks++) {
            int kk = ks * 8;
            unsigned af[4];
            int r = (warpRow + g) * LP + kk + tig;
            af[0] = Ps[r];
            af[1] = Ps[r + 8 * LP];
            af[2] = Ps[r + 4];
            af[3] = Ps[r + 8 * LP + 4];
            #pragma unroll
            for (int nt = 0; nt < 8; nt++) {
                unsigned bf[2];
                int c = nt * 8 + g;
                bf[0] = Vst[(kk + tig) * LV + c];
                bf[1] = Vst[(kk + tig + 4) * LV + c];
                mma_tf32(acc[nt], af, bf);
            }
        }
        __syncthreads();
    }

    float inv0 = 1.f / l0, inv1 = 1.f / l1;
    size_t row0 = (size_t)(b * TSEQ + qb * BQ + warpRow + g);
    #pragma unroll
    for (int nt = 0; nt < 8; nt++) {
        int col = h * DHD + nt * 8 + tig * 2;
        *(float2*)(O + row0 * DMM + col) =
            make_float2(acc[nt][0] * inv0, acc[nt][1] * inv0);
        *(float2*)(O + (row0 + 8) * DMM + col) =
            make_float2(acc[nt][2] * inv1, acc[nt][3] * inv1);
    }
}

// ----------------------------------------------------------------------------
extern "C" void kernel_launch(void* const* d_in, const int* in_sizes, int n_in,
                              void* d_out, int out_size)
{
    const float* x1   = (const float*)d_in[0];
    const float* x2   = (const float*)d_in[1];
    const float* mask = (const float*)d_in[2];
    const float* Wq   = (const float*)d_in[3];
    const float* Wkv  = (const float*)d_in[4];
    const float* Wo   = (const float*)d_in[5];
    const float* bo   = (const float*)d_in[6];
    float* out = (float*)d_out;

    float *q, *kv, *attn;
    cudaGetSymbolAddress((void**)&q, g_q);
    cudaGetSymbolAddress((void**)&kv, g_kv);
    cudaGetSymbolAddress((void**)&attn, g_attn);

    dim3 blk(256);
    // Q proj: output pre-scaled by 1/8, RNA-tf32 bits
    tgemm_kernel<<<dim3(DMM / 128, BT / 128), blk>>>(
        x1, Wq, q, BT, DMM, DMM, nullptr, 0.125f, 1);
    // KV proj: RNA-tf32 bits
    tgemm_kernel<<<dim3(2 * DMM / 128, BT / 128), blk>>>(
        x2, Wkv, kv, BT, 2 * DMM, DMM, nullptr, 1.0f, 1);

    int smem_bytes = (BQ * LQ + BQ * LP + 2 * BK * LK + 2 * BK * LV + TSEQ)
                     * (int)sizeof(unsigned);
    cudaFuncSetAttribute(fattn_kernel, cudaFuncAttributeMaxDynamicSharedMemorySize, smem_bytes);
    fattn_kernel<<<dim3(TSEQ / BQ, HN, BATCH), blk, smem_bytes>>>(q, kv, mask, attn);

    // O proj: full fp32 output + bias
    tgemm_kernel<<<dim3(DMM / 128, BT / 128), blk>>>(
        attn, Wo, out, BT, DMM, DMM, bo, 1.0f, 0);
}